// round 4
// baseline (speedup 1.0000x reference)
#include <cuda_runtime.h>

// Problem constants
#define BB   8
#define NN   1025
#define DD   768
#define HH   12
#define HD   64
#define EE   2304            // 3*DD
#define MR   (BB*NN)         // 8200 rows
#define LNEPS 1e-5f
#define SCALE 0.125f         // 1/sqrt(64)

// Scratch (device globals: no allocation allowed)
__device__ float g_xn [MR*DD];
__device__ float g_qkv[MR*EE];
__device__ float g_q  [BB*HH*NN*HD];
__device__ float g_k  [BB*HH*NN*HD];
__device__ float g_v  [BB*HH*NN*HD];
__device__ float g_att[MR*DD];

// ---------------------------------------------------------------------------
// 1. LayerNorm: one block (256 thr) per row of 768
// ---------------------------------------------------------------------------
__global__ void ln_kernel(const float* __restrict__ x,
                          const float* __restrict__ gam,
                          const float* __restrict__ bet) {
    int row = blockIdx.x;
    const float* xr = x + (size_t)row * DD;
    float* outr = g_xn + (size_t)row * DD;
    int t = threadIdx.x;
    float v0 = xr[t], v1 = xr[t+256], v2 = xr[t+512];
    float s  = v0+v1+v2;
    float sq = v0*v0 + v1*v1 + v2*v2;
    #pragma unroll
    for (int o = 16; o; o >>= 1) {
        s  += __shfl_xor_sync(0xffffffffu, s,  o);
        sq += __shfl_xor_sync(0xffffffffu, sq, o);
    }
    __shared__ float rs[8], rq[8];
    int w = t >> 5, l = t & 31;
    if (!l) { rs[w] = s; rq[w] = sq; }
    __syncthreads();
    if (w == 0) {
        s  = (l < 8) ? rs[l] : 0.f;
        sq = (l < 8) ? rq[l] : 0.f;
        #pragma unroll
        for (int o = 4; o; o >>= 1) {
            s  += __shfl_xor_sync(0xffffffffu, s,  o);
            sq += __shfl_xor_sync(0xffffffffu, sq, o);
        }
        if (!l) { rs[0] = s * (1.f/DD); rq[0] = sq * (1.f/DD); }
    }
    __syncthreads();
    float mu = rs[0];
    float var = rq[0] - mu*mu;
    float rstd = rsqrtf(var + LNEPS);
    outr[t]     = (v0-mu)*rstd*gam[t]     + bet[t];
    outr[t+256] = (v1-mu)*rstd*gam[t+256] + bet[t+256];
    outr[t+512] = (v2-mu)*rstd*gam[t+512] + bet[t+512];
}

// ---------------------------------------------------------------------------
// 2. Generic NT GEMM:  C[M][NC] = A[M][K] * W[NC][K]^T (+bias)
//    64x64 block tile, 4x4 per thread, k-step 16, k-major smem (pad 68)
// ---------------------------------------------------------------------------
template<int M, int NC, int K, bool BIAS>
__device__ __forceinline__ void gemm_body(const float* __restrict__ A,
                                          const float* __restrict__ W,
                                          const float* __restrict__ bias,
                                          float* __restrict__ C) {
    __shared__ float As[16][68];
    __shared__ float Ws[16][68];
    int tid = threadIdx.x;
    int tx = tid & 15, ty = tid >> 4;
    int tx4 = tx*4, ty4 = ty*4;
    int lr = tid >> 2, lk = tid & 3;
    int rowBase = blockIdx.x * 64;
    int colBase = blockIdx.y * 64;
    float acc[4][4] = {};
    int aRow = rowBase + lr;
    const float* aPtr = A + (size_t)aRow * K + lk*4;
    const float* wPtr = W + (size_t)(colBase + lr) * K + lk*4;
    bool aOk = (aRow < M);
    for (int kt = 0; kt < K; kt += 16) {
        float4 av = aOk ? *(const float4*)(aPtr + kt) : make_float4(0.f,0.f,0.f,0.f);
        float4 wv = *(const float4*)(wPtr + kt);
        As[lk*4+0][lr] = av.x; As[lk*4+1][lr] = av.y;
        As[lk*4+2][lr] = av.z; As[lk*4+3][lr] = av.w;
        Ws[lk*4+0][lr] = wv.x; Ws[lk*4+1][lr] = wv.y;
        Ws[lk*4+2][lr] = wv.z; Ws[lk*4+3][lr] = wv.w;
        __syncthreads();
        #pragma unroll
        for (int kk = 0; kk < 16; kk++) {
            const float4 a = *(const float4*)(&As[kk][ty4]);
            const float4 b = *(const float4*)(&Ws[kk][tx4]);
            acc[0][0] += a.x*b.x; acc[0][1] += a.x*b.y; acc[0][2] += a.x*b.z; acc[0][3] += a.x*b.w;
            acc[1][0] += a.y*b.x; acc[1][1] += a.y*b.y; acc[1][2] += a.y*b.z; acc[1][3] += a.y*b.w;
            acc[2][0] += a.z*b.x; acc[2][1] += a.z*b.y; acc[2][2] += a.z*b.z; acc[2][3] += a.z*b.w;
            acc[3][0] += a.w*b.x; acc[3][1] += a.w*b.y; acc[3][2] += a.w*b.z; acc[3][3] += a.w*b.w;
        }
        __syncthreads();
    }
    float4 bv = make_float4(0.f,0.f,0.f,0.f);
    if (BIAS) bv = *(const float4*)(bias + colBase + tx4);
    #pragma unroll
    for (int i = 0; i < 4; i++) {
        int r = rowBase + ty4 + i;
        if (r < M) {
            float4 o;
            o.x = acc[i][0] + bv.x;
            o.y = acc[i][1] + bv.y;
            o.z = acc[i][2] + bv.z;
            o.w = acc[i][3] + bv.w;
            *(float4*)(&C[(size_t)r*NC + colBase + tx4]) = o;
        }
    }
}

__global__ void gemm_qkv_kernel(const float* __restrict__ W) {
    gemm_body<MR, EE, DD, false>(g_xn, W, nullptr, g_qkv);
}
__global__ void gemm_proj_kernel(const float* __restrict__ W,
                                 const float* __restrict__ bias,
                                 float* __restrict__ C) {
    gemm_body<MR, DD, DD, true>(g_att, W, bias, C);
}

// ---------------------------------------------------------------------------
// 3. RoPE + scatter qkv -> q,k,v in [B,H,N,64] layout
//    one thread per rotation pair (32 pairs per head-token)
// ---------------------------------------------------------------------------
__global__ void rope_kernel() {
    int idx = blockIdx.x * 256 + threadIdx.x;
    if (idx >= MR * HH * 32) return;
    int p   = idx & 31;
    int tmp = idx >> 5;
    int h   = tmp % HH;
    int row = tmp / HH;          // b*NN + n
    int n = row % NN;
    int b = row / NN;
    int j, d0, t;
    if (p < 16) {
        j = p; d0 = 2*p;
        t = (n == 0) ? 0 : (n-1) / 32;        // row id
    } else {
        j = p - 16; d0 = 32 + 2*(p-16);
        t = (n == 0) ? 0 : (n-1) % 32;        // col id
    }
    // inv_freq = 10000^(-j/16) = exp(-j * ln(10000)/16)
    float theta = (float)t * expf(-(float)j * 0.5756462732485115f);
    float s, c;
    sincosf(theta, &s, &c);
    const float* base = g_qkv + (size_t)row * EE + h*64;
    size_t o = ((size_t)(b*HH + h) * NN + n) * 64 + d0;
    float qe = base[d0],      qo = base[d0+1];
    g_q[o]   = qe*c - qo*s;   g_q[o+1] = qo*c + qe*s;
    float ke = base[768+d0],  ko = base[768+d0+1];
    g_k[o]   = ke*c - ko*s;   g_k[o+1] = ko*c + ke*s;
    g_v[o]   = base[1536+d0]; g_v[o+1] = base[1536+d0+1];
}

// ---------------------------------------------------------------------------
// 4. Fused flash-style attention: grid (ceil(N/64), H, B), 256 threads
//    smem: Qs[64][68] (d-major), Ks[64][68] (d-major), Vs[64][68], Ps[64][68]
// ---------------------------------------------------------------------------
#define LDP 68
__global__ void attn_kernel() {
    extern __shared__ float sm[];
    float* Qs = sm;               // Qs[d*LDP + i]
    float* Ks = Qs + 64*LDP;      // Ks[d*LDP + j]
    float* Vs = Ks + 64*LDP;      // Vs[j*LDP + d]
    float* Ps = Vs + 64*LDP;      // Ps[i*LDP + j]
    float* sm_m = Ps + 64*LDP;
    float* sm_l = sm_m + 64;
    float* sm_a = sm_l + 64;

    int tid = threadIdx.x;
    int tx = tid & 15, ty = tid >> 4;
    int tx4 = tx*4, ty4 = ty*4;
    int qb = blockIdx.x, h = blockIdx.y, b = blockIdx.z;
    size_t headOff = (size_t)(b*HH + h) * NN * 64;

    // load Q tile (transposed to d-major), zero-pad out-of-range rows
    #pragma unroll
    for (int u = 0; u < 4; u++) {
        int li = tid + u*256;
        int r = li >> 4, q4 = li & 15;
        int n = qb*64 + r;
        float4 val = (n < NN) ? *(const float4*)(g_q + headOff + (size_t)n*64 + q4*4)
                              : make_float4(0.f,0.f,0.f,0.f);
        Qs[(q4*4+0)*LDP + r] = val.x;
        Qs[(q4*4+1)*LDP + r] = val.y;
        Qs[(q4*4+2)*LDP + r] = val.z;
        Qs[(q4*4+3)*LDP + r] = val.w;
    }
    if (tid < 64) { sm_m[tid] = -1e30f; sm_l[tid] = 0.f; }

    float acc[4][4] = {};

    for (int kb = 0; kb < (NN + 63)/64; kb++) {
        // load K (transposed) and V tiles, zero-padded
        #pragma unroll
        for (int u = 0; u < 4; u++) {
            int li = tid + u*256;
            int r = li >> 4, q4 = li & 15;
            int n = kb*64 + r;
            float4 kv, vv;
            if (n < NN) {
                kv = *(const float4*)(g_k + headOff + (size_t)n*64 + q4*4);
                vv = *(const float4*)(g_v + headOff + (size_t)n*64 + q4*4);
            } else {
                kv = make_float4(0.f,0.f,0.f,0.f);
                vv = kv;
            }
            Ks[(q4*4+0)*LDP + r] = kv.x;
            Ks[(q4*4+1)*LDP + r] = kv.y;
            Ks[(q4*4+2)*LDP + r] = kv.z;
            Ks[(q4*4+3)*LDP + r] = kv.w;
            *(float4*)(&Vs[r*LDP + q4*4]) = vv;
        }
        __syncthreads();

        // S = Q @ K^T
        float s4[4][4] = {};
        #pragma unroll 8
        for (int d = 0; d < 64; d++) {
            const float4 a = *(const float4*)(&Qs[d*LDP + ty4]);
            const float4 bb = *(const float4*)(&Ks[d*LDP + tx4]);
            s4[0][0] += a.x*bb.x; s4[0][1] += a.x*bb.y; s4[0][2] += a.x*bb.z; s4[0][3] += a.x*bb.w;
            s4[1][0] += a.y*bb.x; s4[1][1] += a.y*bb.y; s4[1][2] += a.y*bb.z; s4[1][3] += a.y*bb.w;
            s4[2][0] += a.z*bb.x; s4[2][1] += a.z*bb.y; s4[2][2] += a.z*bb.z; s4[2][3] += a.z*bb.w;
            s4[3][0] += a.w*bb.x; s4[3][1] += a.w*bb.y; s4[3][2] += a.w*bb.z; s4[3][3] += a.w*bb.w;
        }
        // scaled + masked store into Ps
        int colg = kb*64 + tx4;
        #pragma unroll
        for (int i = 0; i < 4; i++) {
            float4 o;
            o.x = (colg+0 < NN) ? s4[i][0]*SCALE : -1e30f;
            o.y = (colg+1 < NN) ? s4[i][1]*SCALE : -1e30f;
            o.z = (colg+2 < NN) ? s4[i][2]*SCALE : -1e30f;
            o.w = (colg+3 < NN) ? s4[i][3]*SCALE : -1e30f;
            *(float4*)(&Ps[(ty4+i)*LDP + tx4]) = o;
        }
        __syncthreads();

        // online softmax: 4 threads per row
        {
            int r = tid >> 2, seg = tid & 3;
            const float* pr = &Ps[r*LDP + seg*16];
            float mx = -1e30f;
            #pragma unroll
            for (int u = 0; u < 16; u++) mx = fmaxf(mx, pr[u]);
            mx = fmaxf(mx, __shfl_xor_sync(0xffffffffu, mx, 1));
            mx = fmaxf(mx, __shfl_xor_sync(0xffffffffu, mx, 2));
            float m_old = sm_m[r];
            float m_new = fmaxf(m_old, mx);
            float sum = 0.f;
            float* prw = &Ps[r*LDP + seg*16];
            #pragma unroll
            for (int u = 0; u < 16; u++) {
                float e = __expf(prw[u] - m_new);
                prw[u] = e;
                sum += e;
            }
            sum += __shfl_xor_sync(0xffffffffu, sum, 1);
            sum += __shfl_xor_sync(0xffffffffu, sum, 2);
            if (seg == 0) {
                float alpha = __expf(m_old - m_new);
                sm_a[r] = alpha;
                sm_l[r] = sm_l[r]*alpha + sum;
                sm_m[r] = m_new;
            }
        }
        __syncthreads();

        // rescale accumulator and add P @ V
        float al0 = sm_a[ty4+0], al1 = sm_a[ty4+1], al2 = sm_a[ty4+2], al3 = sm_a[ty4+3];
        #pragma unroll
        for (int j = 0; j < 4; j++) {
            acc[0][j] *= al0; acc[1][j] *= al1; acc[2][j] *= al2; acc[3][j] *= al3;
        }
        #pragma unroll 8
        for (int jj = 0; jj < 64; jj++) {
            float a0 = Ps[(ty4+0)*LDP + jj];
            float a1 = Ps[(ty4+1)*LDP + jj];
            float a2 = Ps[(ty4+2)*LDP + jj];
            float a3 = Ps[(ty4+3)*LDP + jj];
            const float4 bb = *(const float4*)(&Vs[jj*LDP + tx4]);
            acc[0][0] += a0*bb.x; acc[0][1] += a0*bb.y; acc[0][2] += a0*bb.z; acc[0][3] += a0*bb.w;
            acc[1][0] += a1*bb.x; acc[1][1] += a1*bb.y; acc[1][2] += a1*bb.z; acc[1][3] += a1*bb.w;
            acc[2][0] += a2*bb.x; acc[2][1] += a2*bb.y; acc[2][2] += a2*bb.z; acc[2][3] += a2*bb.w;
            acc[3][0] += a3*bb.x; acc[3][1] += a3*bb.y; acc[3][2] += a3*bb.z; acc[3][3] += a3*bb.w;
        }
        __syncthreads();
    }

    // normalize and write out to [b][n][h*64+d]
    #pragma unroll
    for (int i = 0; i < 4; i++) {
        int n = qb*64 + ty4 + i;
        if (n < NN) {
            float linv = 1.f / sm_l[ty4+i];
            float4 o;
            o.x = acc[i][0]*linv; o.y = acc[i][1]*linv;
            o.z = acc[i][2]*linv; o.w = acc[i][3]*linv;
            *(float4*)(&g_att[((size_t)b*NN + n)*DD + h*64 + tx4]) = o;
        }
    }
}

// ---------------------------------------------------------------------------
// Launch
// ---------------------------------------------------------------------------
extern "C" void kernel_launch(void* const* d_in, const int* in_sizes, int n_in,
                              void* d_out, int out_size) {
    const float* x      = (const float*)d_in[0];
    const float* ln_g   = (const float*)d_in[1];
    const float* ln_b   = (const float*)d_in[2];
    const float* w_qkv  = (const float*)d_in[3];
    const float* w_proj = (const float*)d_in[4];
    const float* b_proj = (const float*)d_in[5];
    float* out = (float*)d_out;

    static_assert(4*64*LDP + 3*64 == 17600, "smem layout");
    const int ATT_SMEM = (4*64*LDP + 3*64) * sizeof(float);   // 70400 B
    cudaFuncSetAttribute(attn_kernel, cudaFuncAttributeMaxDynamicSharedMemorySize, ATT_SMEM);

    ln_kernel<<<MR, 256>>>(x, ln_g, ln_b);
    gemm_qkv_kernel<<<dim3((MR+63)/64, EE/64), 256>>>(w_qkv);
    rope_kernel<<<(MR*HH*32 + 255)/256, 256>>>();
    attn_kernel<<<dim3((NN+63)/64, HH, BB), 256, ATT_SMEM>>>();
    gemm_proj_kernel<<<dim3((MR+63)/64, DD/64), 256>>>(w_proj, b_proj, out);
}

// round 5
// speedup vs baseline: 2.2259x; 2.2259x over previous
#include <cuda_runtime.h>

// Problem constants
#define BB   8
#define NN   1025
#define DD   768
#define HH   12
#define HD   64
#define EE   2304            // 3*DD
#define MR   (BB*NN)         // 8200 rows
#define LNEPS 1e-5f
#define SCALE 0.125f         // 1/sqrt(64)

// Scratch (device globals: no allocation allowed)
__device__ float g_xn [MR*DD];
__device__ float g_qkv[MR*EE];
__device__ float g_q  [BB*HH*NN*HD];
__device__ float g_k  [BB*HH*NN*HD];
__device__ float g_v  [BB*HH*NN*HD];
__device__ float g_att[MR*DD];

// ---------------------------------------------------------------------------
// helpers: tf32 round + mma.sync m16n8k8 (A row-major, B col-major)
// ---------------------------------------------------------------------------
__device__ __forceinline__ float f2tf32(float f) {
    unsigned u;
    asm("cvt.rna.tf32.f32 %0, %1;" : "=r"(u) : "f"(f));
    return __uint_as_float(u);
}

__device__ __forceinline__ void mma_tf32(float& d0, float& d1, float& d2, float& d3,
                                         unsigned a0, unsigned a1, unsigned a2, unsigned a3,
                                         unsigned b0, unsigned b1) {
    asm volatile(
        "mma.sync.aligned.m16n8k8.row.col.f32.tf32.tf32.f32 "
        "{%0,%1,%2,%3},{%4,%5,%6,%7},{%8,%9},{%0,%1,%2,%3};"
        : "+f"(d0), "+f"(d1), "+f"(d2), "+f"(d3)
        : "r"(a0), "r"(a1), "r"(a2), "r"(a3), "r"(b0), "r"(b1));
}

// ---------------------------------------------------------------------------
// 1. LayerNorm: one block (256 thr) per row of 768
// ---------------------------------------------------------------------------
__global__ void ln_kernel(const float* __restrict__ x,
                          const float* __restrict__ gam,
                          const float* __restrict__ bet) {
    int row = blockIdx.x;
    const float* xr = x + (size_t)row * DD;
    float* outr = g_xn + (size_t)row * DD;
    int t = threadIdx.x;
    float v0 = xr[t], v1 = xr[t+256], v2 = xr[t+512];
    float s  = v0+v1+v2;
    float sq = v0*v0 + v1*v1 + v2*v2;
    #pragma unroll
    for (int o = 16; o; o >>= 1) {
        s  += __shfl_xor_sync(0xffffffffu, s,  o);
        sq += __shfl_xor_sync(0xffffffffu, sq, o);
    }
    __shared__ float rs[8], rq[8];
    int w = t >> 5, l = t & 31;
    if (!l) { rs[w] = s; rq[w] = sq; }
    __syncthreads();
    if (w == 0) {
        s  = (l < 8) ? rs[l] : 0.f;
        sq = (l < 8) ? rq[l] : 0.f;
        #pragma unroll
        for (int o = 4; o; o >>= 1) {
            s  += __shfl_xor_sync(0xffffffffu, s,  o);
            sq += __shfl_xor_sync(0xffffffffu, sq, o);
        }
        if (!l) { rs[0] = s * (1.f/DD); rq[0] = sq * (1.f/DD); }
    }
    __syncthreads();
    float mu = rs[0];
    float var = rq[0] - mu*mu;
    float rstd = rsqrtf(var + LNEPS);
    outr[t]     = (v0-mu)*rstd*gam[t]     + bet[t];
    outr[t+256] = (v1-mu)*rstd*gam[t+256] + bet[t+256];
    outr[t+512] = (v2-mu)*rstd*gam[t+512] + bet[t+512];
}

// ---------------------------------------------------------------------------
// 2. TF32 tensor-core NT GEMM: C[M][NC] = A[M][K] * W[NC][K]^T (+bias)
//    128x64 block tile, 8 warps (4x2), 32x32 per warp, k-step 16
// ---------------------------------------------------------------------------
template<int M, int NC, int K, bool BIAS>
__device__ __forceinline__ void gemm_mma_body(const float* __restrict__ A,
                                              const float* __restrict__ W,
                                              const float* __restrict__ bias,
                                              float* __restrict__ C) {
    __shared__ float As[128][20];
    __shared__ float Ws[64][20];
    int tid = threadIdx.x;
    int w = tid >> 5, lane = tid & 31;
    int wm = w & 3;          // row quadrant: 32*wm
    int wn = w >> 2;         // col half:    32*wn
    int g  = lane >> 2;      // group id 0..7
    int tg = lane & 3;       // thread-in-group 0..3
    int rowBase = blockIdx.x * 128;
    int colBase = blockIdx.y * 64;

    float acc[2][4][4] = {};     // [mtile][ntile][c0..c3]

    int sr = tid >> 2;           // staging row (0..63)
    int sc = (tid & 3) * 4;      // staging col (0..12)

    for (int kt = 0; kt < K; kt += 16) {
        #pragma unroll
        for (int p = 0; p < 2; p++) {
            int r = sr + p * 64;
            int gr = rowBase + r;
            float4 v = (gr < M) ? *(const float4*)(A + (size_t)gr * K + kt + sc)
                                : make_float4(0.f, 0.f, 0.f, 0.f);
            As[r][sc]   = f2tf32(v.x);
            As[r][sc+1] = f2tf32(v.y);
            As[r][sc+2] = f2tf32(v.z);
            As[r][sc+3] = f2tf32(v.w);
        }
        {
            float4 v = *(const float4*)(W + (size_t)(colBase + sr) * K + kt + sc);
            Ws[sr][sc]   = f2tf32(v.x);
            Ws[sr][sc+1] = f2tf32(v.y);
            Ws[sr][sc+2] = f2tf32(v.z);
            Ws[sr][sc+3] = f2tf32(v.w);
        }
        __syncthreads();

        #pragma unroll
        for (int ks = 0; ks < 16; ks += 8) {
            unsigned a[2][4], b[4][2];
            #pragma unroll
            for (int mt = 0; mt < 2; mt++) {
                int r0 = wm*32 + mt*16 + g;
                a[mt][0] = __float_as_uint(As[r0  ][ks+tg  ]);
                a[mt][1] = __float_as_uint(As[r0+8][ks+tg  ]);
                a[mt][2] = __float_as_uint(As[r0  ][ks+tg+4]);
                a[mt][3] = __float_as_uint(As[r0+8][ks+tg+4]);
            }
            #pragma unroll
            for (int nt = 0; nt < 4; nt++) {
                int c0 = wn*32 + nt*8 + g;
                b[nt][0] = __float_as_uint(Ws[c0][ks+tg  ]);
                b[nt][1] = __float_as_uint(Ws[c0][ks+tg+4]);
            }
            #pragma unroll
            for (int mt = 0; mt < 2; mt++)
                #pragma unroll
                for (int nt = 0; nt < 4; nt++)
                    mma_tf32(acc[mt][nt][0], acc[mt][nt][1], acc[mt][nt][2], acc[mt][nt][3],
                             a[mt][0], a[mt][1], a[mt][2], a[mt][3],
                             b[nt][0], b[nt][1]);
        }
        __syncthreads();
    }

    #pragma unroll
    for (int mt = 0; mt < 2; mt++) {
        int r_lo = rowBase + wm*32 + mt*16 + g;
        int r_hi = r_lo + 8;
        #pragma unroll
        for (int nt = 0; nt < 4; nt++) {
            int c = colBase + wn*32 + nt*8 + tg*2;
            float bx = 0.f, by = 0.f;
            if (BIAS) { bx = bias[c]; by = bias[c+1]; }
            if (r_lo < M) {
                float2 o; o.x = acc[mt][nt][0] + bx; o.y = acc[mt][nt][1] + by;
                *(float2*)(&C[(size_t)r_lo * NC + c]) = o;
            }
            if (r_hi < M) {
                float2 o; o.x = acc[mt][nt][2] + bx; o.y = acc[mt][nt][3] + by;
                *(float2*)(&C[(size_t)r_hi * NC + c]) = o;
            }
        }
    }
}

__global__ void gemm_qkv_kernel(const float* __restrict__ W) {
    gemm_mma_body<MR, EE, DD, false>(g_xn, W, nullptr, g_qkv);
}
__global__ void gemm_proj_kernel(const float* __restrict__ W,
                                 const float* __restrict__ bias,
                                 float* __restrict__ C) {
    gemm_mma_body<MR, DD, DD, true>(g_att, W, bias, C);
}

// ---------------------------------------------------------------------------
// 3. RoPE + scatter qkv -> q,k,v in [B,H,N,64] layout (fp32)
// ---------------------------------------------------------------------------
__global__ void rope_kernel() {
    int idx = blockIdx.x * 256 + threadIdx.x;
    if (idx >= MR * HH * 32) return;
    int p   = idx & 31;
    int tmp = idx >> 5;
    int h   = tmp % HH;
    int row = tmp / HH;          // b*NN + n
    int n = row % NN;
    int b = row / NN;
    int j, d0, t;
    if (p < 16) {
        j = p; d0 = 2*p;
        t = (n == 0) ? 0 : (n-1) / 32;        // row id
    } else {
        j = p - 16; d0 = 32 + 2*(p-16);
        t = (n == 0) ? 0 : (n-1) % 32;        // col id
    }
    float theta = (float)t * expf(-(float)j * 0.5756462732485115f);
    float s, c;
    sincosf(theta, &s, &c);
    const float* base = g_qkv + (size_t)row * EE + h*64;
    size_t o = ((size_t)(b*HH + h) * NN + n) * 64 + d0;
    float qe = base[d0],      qo = base[d0+1];
    g_q[o]   = qe*c - qo*s;   g_q[o+1] = qo*c + qe*s;
    float ke = base[768+d0],  ko = base[768+d0+1];
    g_k[o]   = ke*c - ko*s;   g_k[o+1] = ko*c + ke*s;
    g_v[o]   = base[1536+d0]; g_v[o+1] = base[1536+d0+1];
}

// ---------------------------------------------------------------------------
// 4. Flash attention with TF32 mma: grid (ceil(N/64), H, B), 256 threads
//    smem: Qs[64][68] (row-major), Ks[64][68] (row-major), Vt[64][68] (d-major),
//          Ps[64][68] (row-major), m/l/a[64]
//    Warp w: rows 16*(w&3), cols/dims 32*(w>>2)
// ---------------------------------------------------------------------------
#define LDP 68
__global__ void attn_kernel() {
    extern __shared__ float sm[];
    float* Qs = sm;               // Qs[r*LDP + d]     (tf32)
    float* Ks = Qs + 64*LDP;      // Ks[j*LDP + d]     (tf32)  == B col-major
    float* Vt = Ks + 64*LDP;      // Vt[d*LDP + j]     (tf32)  == B col-major
    float* Ps = Vt + 64*LDP;      // Ps[r*LDP + j]
    float* sm_m = Ps + 64*LDP;
    float* sm_l = sm_m + 64;
    float* sm_a = sm_l + 64;

    int tid = threadIdx.x;
    int w = tid >> 5, lane = tid & 31;
    int wm = w & 3;
    int wn = w >> 2;
    int g  = lane >> 2;
    int tg = lane & 3;
    int qb = blockIdx.x, h = blockIdx.y, b = blockIdx.z;
    size_t headOff = (size_t)(b*HH + h) * NN * 64;

    // load Q tile row-major (tf32-rounded), zero-pad OOB rows
    #pragma unroll
    for (int u = 0; u < 4; u++) {
        int li = tid + u*256;
        int r = li >> 4, q4 = li & 15;
        int n = qb*64 + r;
        float4 val = (n < NN) ? *(const float4*)(g_q + headOff + (size_t)n*64 + q4*4)
                              : make_float4(0.f,0.f,0.f,0.f);
        float* dst = &Qs[r*LDP + q4*4];
        dst[0] = f2tf32(val.x); dst[1] = f2tf32(val.y);
        dst[2] = f2tf32(val.z); dst[3] = f2tf32(val.w);
    }
    if (tid < 64) { sm_m[tid] = -1e30f; sm_l[tid] = 0.f; }

    float acc[4][4] = {};   // PV accumulator: [ntile][c0..c3]

    for (int kb = 0; kb < (NN + 63)/64; kb++) {
        // stage K (row-major) and V (transposed, d-major), tf32-rounded
        #pragma unroll
        for (int u = 0; u < 4; u++) {
            int li = tid + u*256;
            int r = li >> 4, q4 = li & 15;
            int n = kb*64 + r;
            float4 kv, vv;
            if (n < NN) {
                kv = *(const float4*)(g_k + headOff + (size_t)n*64 + q4*4);
                vv = *(const float4*)(g_v + headOff + (size_t)n*64 + q4*4);
            } else {
                kv = make_float4(0.f,0.f,0.f,0.f);
                vv = kv;
            }
            float* kd = &Ks[r*LDP + q4*4];
            kd[0] = f2tf32(kv.x); kd[1] = f2tf32(kv.y);
            kd[2] = f2tf32(kv.z); kd[3] = f2tf32(kv.w);
            Vt[(q4*4+0)*LDP + r] = f2tf32(vv.x);
            Vt[(q4*4+1)*LDP + r] = f2tf32(vv.y);
            Vt[(q4*4+2)*LDP + r] = f2tf32(vv.z);
            Vt[(q4*4+3)*LDP + r] = f2tf32(vv.w);
        }
        __syncthreads();

        // S = Q @ K^T via mma  (warp tile 16x32: 4 ntiles)
        float s4[4][4] = {};
        #pragma unroll
        for (int d0 = 0; d0 < 64; d0 += 8) {
            unsigned a0, a1, a2, a3;
            {
                int r0 = wm*16 + g;
                a0 = __float_as_uint(Qs[ r0   *LDP + d0+tg  ]);
                a1 = __float_as_uint(Qs[(r0+8)*LDP + d0+tg  ]);
                a2 = __float_as_uint(Qs[ r0   *LDP + d0+tg+4]);
                a3 = __float_as_uint(Qs[(r0+8)*LDP + d0+tg+4]);
            }
            #pragma unroll
            for (int nt = 0; nt < 4; nt++) {
                int c0 = wn*32 + nt*8 + g;
                unsigned b0 = __float_as_uint(Ks[c0*LDP + d0+tg  ]);
                unsigned b1 = __float_as_uint(Ks[c0*LDP + d0+tg+4]);
                mma_tf32(s4[nt][0], s4[nt][1], s4[nt][2], s4[nt][3],
                         a0, a1, a2, a3, b0, b1);
            }
        }

        // scatter S fragments to Ps (scaled, masked)
        {
            int r_lo = wm*16 + g;
            int r_hi = r_lo + 8;
            #pragma unroll
            for (int nt = 0; nt < 4; nt++) {
                int c = wn*32 + nt*8 + tg*2;
                int cg = kb*64 + c;
                float v0 = (cg   < NN) ? s4[nt][0]*SCALE : -1e30f;
                float v1 = (cg+1 < NN) ? s4[nt][1]*SCALE : -1e30f;
                float v2 = (cg   < NN) ? s4[nt][2]*SCALE : -1e30f;
                float v3 = (cg+1 < NN) ? s4[nt][3]*SCALE : -1e30f;
                Ps[r_lo*LDP + c] = v0; Ps[r_lo*LDP + c+1] = v1;
                Ps[r_hi*LDP + c] = v2; Ps[r_hi*LDP + c+1] = v3;
            }
        }
        __syncthreads();

        // online softmax: 4 threads per row; write back tf32-rounded exp
        {
            int r = tid >> 2, seg = tid & 3;
            float* pr = &Ps[r*LDP + seg*16];
            float mx = -1e30f;
            #pragma unroll
            for (int u = 0; u < 16; u++) mx = fmaxf(mx, pr[u]);
            mx = fmaxf(mx, __shfl_xor_sync(0xffffffffu, mx, 1));
            mx = fmaxf(mx, __shfl_xor_sync(0xffffffffu, mx, 2));
            float m_old = sm_m[r];
            float m_new = fmaxf(m_old, mx);
            float sum = 0.f;
            #pragma unroll
            for (int u = 0; u < 16; u++) {
                float e = f2tf32(__expf(pr[u] - m_new));
                pr[u] = e;
                sum += e;
            }
            sum += __shfl_xor_sync(0xffffffffu, sum, 1);
            sum += __shfl_xor_sync(0xffffffffu, sum, 2);
            if (seg == 0) {
                float alpha = __expf(m_old - m_new);
                sm_a[r] = alpha;
                sm_l[r] = sm_l[r]*alpha + sum;
                sm_m[r] = m_new;
            }
        }
        __syncthreads();

        // rescale accumulator, then acc += P @ V via mma
        {
            int r_lo = wm*16 + g;
            float al0 = sm_a[r_lo], al1 = sm_a[r_lo + 8];
            #pragma unroll
            for (int nt = 0; nt < 4; nt++) {
                acc[nt][0] *= al0; acc[nt][1] *= al0;
                acc[nt][2] *= al1; acc[nt][3] *= al1;
            }
        }
        #pragma unroll
        for (int j0 = 0; j0 < 64; j0 += 8) {
            unsigned a0, a1, a2, a3;
            {
                int r0 = wm*16 + g;
                a0 = __float_as_uint(Ps[ r0   *LDP + j0+tg  ]);
                a1 = __float_as_uint(Ps[(r0+8)*LDP + j0+tg  ]);
                a2 = __float_as_uint(Ps[ r0   *LDP + j0+tg+4]);
                a3 = __float_as_uint(Ps[(r0+8)*LDP + j0+tg+4]);
            }
            #pragma unroll
            for (int nt = 0; nt < 4; nt++) {
                int c0 = wn*32 + nt*8 + g;
                unsigned b0 = __float_as_uint(Vt[c0*LDP + j0+tg  ]);
                unsigned b1 = __float_as_uint(Vt[c0*LDP + j0+tg+4]);
                mma_tf32(acc[nt][0], acc[nt][1], acc[nt][2], acc[nt][3],
                         a0, a1, a2, a3, b0, b1);
            }
        }
        __syncthreads();
    }

    // normalize and write out to [b][n][h*64+d]
    {
        int r_lo = wm*16 + g;
        int r_hi = r_lo + 8;
        int n_lo = qb*64 + r_lo;
        int n_hi = qb*64 + r_hi;
        float linv0 = 1.f / sm_l[r_lo];
        float linv1 = 1.f / sm_l[r_hi];
        #pragma unroll
        for (int nt = 0; nt < 4; nt++) {
            int d = wn*32 + nt*8 + tg*2;
            if (n_lo < NN) {
                float2 o; o.x = acc[nt][0]*linv0; o.y = acc[nt][1]*linv0;
                *(float2*)(&g_att[((size_t)b*NN + n_lo)*DD + h*64 + d]) = o;
            }
            if (n_hi < NN) {
                float2 o; o.x = acc[nt][2]*linv1; o.y = acc[nt][3]*linv1;
                *(float2*)(&g_att[((size_t)b*NN + n_hi)*DD + h*64 + d]) = o;
            }
        }
    }
}

// ---------------------------------------------------------------------------
// Launch
// ---------------------------------------------------------------------------
extern "C" void kernel_launch(void* const* d_in, const int* in_sizes, int n_in,
                              void* d_out, int out_size) {
    const float* x      = (const float*)d_in[0];
    const float* ln_g   = (const float*)d_in[1];
    const float* ln_b   = (const float*)d_in[2];
    const float* w_qkv  = (const float*)d_in[3];
    const float* w_proj = (const float*)d_in[4];
    const float* b_proj = (const float*)d_in[5];
    float* out = (float*)d_out;

    const int ATT_SMEM = (4*64*LDP + 3*64) * sizeof(float);   // 70400 B
    cudaFuncSetAttribute(attn_kernel, cudaFuncAttributeMaxDynamicSharedMemorySize, ATT_SMEM);

    ln_kernel<<<MR, 256>>>(x, ln_g, ln_b);
    gemm_qkv_kernel<<<dim3((MR+127)/128, EE/64), 256>>>(w_qkv);
    rope_kernel<<<(MR*HH*32 + 255)/256, 256>>>();
    attn_kernel<<<dim3((NN+63)/64, HH, BB), 256, ATT_SMEM>>>();
    gemm_proj_kernel<<<dim3((MR+127)/128, DD/64), 256>>>(w_proj, b_proj, out);
}

// round 9
// speedup vs baseline: 3.0467x; 1.3688x over previous
#include <cuda_runtime.h>

// Problem constants
#define BB   8
#define NN   1025
#define DD   768
#define HH   12
#define HD   64
#define EE   2304            // 3*DD
#define MR   (BB*NN)         // 8200 rows
#define LNEPS 1e-5f

// Scratch (device globals: no allocation allowed)
__device__ float g_xn [MR*DD];
__device__ float g_qkv[MR*EE];
__device__ float g_q  [BB*HH*NN*HD];
__device__ float g_k  [BB*HH*NN*HD];
__device__ float g_v  [BB*HH*NN*HD];
__device__ float g_att[MR*DD];
__device__ float g_wq [EE*DD];       // tf32-rounded w_qkv
__device__ float g_wp [DD*DD];       // tf32-rounded w_proj

// ---------------------------------------------------------------------------
// helpers
// ---------------------------------------------------------------------------
__device__ __forceinline__ float f2tf32(float f) {
    unsigned u;
    asm("cvt.rna.tf32.f32 %0, %1;" : "=r"(u) : "f"(f));
    return __uint_as_float(u);
}

__device__ __forceinline__ void mma_tf32(float& d0, float& d1, float& d2, float& d3,
                                         unsigned a0, unsigned a1, unsigned a2, unsigned a3,
                                         unsigned b0, unsigned b1) {
    asm volatile(
        "mma.sync.aligned.m16n8k8.row.col.f32.tf32.tf32.f32 "
        "{%0,%1,%2,%3},{%4,%5,%6,%7},{%8,%9},{%0,%1,%2,%3};"
        : "+f"(d0), "+f"(d1), "+f"(d2), "+f"(d3)
        : "r"(a0), "r"(a1), "r"(a2), "r"(a3), "r"(b0), "r"(b1));
}

__device__ __forceinline__ void cpa16(const void* smemp, const void* g, bool pred) {
    unsigned sa = (unsigned)__cvta_generic_to_shared(smemp);
    int sz = pred ? 16 : 0;
    asm volatile("cp.async.cg.shared.global [%0], [%1], 16, %2;"
                 :: "r"(sa), "l"(g), "r"(sz));
}
#define CP_COMMIT() asm volatile("cp.async.commit_group;")
#define CP_WAIT(n)  asm volatile("cp.async.wait_group %0;" :: "n"(n))

// ---------------------------------------------------------------------------
// 0. Pre-round weights to tf32 (vectorized)
// ---------------------------------------------------------------------------
__global__ void roundw_kernel(const float4* __restrict__ wq,
                              const float4* __restrict__ wp) {
    const int NQ = EE*DD/4, NP = DD*DD/4;
    int i = blockIdx.x * 256 + threadIdx.x;
    if (i < NQ) {
        float4 v = wq[i];
        v.x = f2tf32(v.x); v.y = f2tf32(v.y); v.z = f2tf32(v.z); v.w = f2tf32(v.w);
        ((float4*)g_wq)[i] = v;
    } else if (i - NQ < NP) {
        int j = i - NQ;
        float4 v = wp[j];
        v.x = f2tf32(v.x); v.y = f2tf32(v.y); v.z = f2tf32(v.z); v.w = f2tf32(v.w);
        ((float4*)g_wp)[j] = v;
    }
}

// ---------------------------------------------------------------------------
// 1. LayerNorm: one block (256 thr) per row; tf32-rounded output
// ---------------------------------------------------------------------------
__global__ void ln_kernel(const float* __restrict__ x,
                          const float* __restrict__ gam,
                          const float* __restrict__ bet) {
    int row = blockIdx.x;
    const float* xr = x + (size_t)row * DD;
    float* outr = g_xn + (size_t)row * DD;
    int t = threadIdx.x;
    float v0 = xr[t], v1 = xr[t+256], v2 = xr[t+512];
    float s  = v0+v1+v2;
    float sq = v0*v0 + v1*v1 + v2*v2;
    #pragma unroll
    for (int o = 16; o; o >>= 1) {
        s  += __shfl_xor_sync(0xffffffffu, s,  o);
        sq += __shfl_xor_sync(0xffffffffu, sq, o);
    }
    __shared__ float rs[8], rq[8];
    int w = t >> 5, l = t & 31;
    if (!l) { rs[w] = s; rq[w] = sq; }
    __syncthreads();
    if (w == 0) {
        s  = (l < 8) ? rs[l] : 0.f;
        sq = (l < 8) ? rq[l] : 0.f;
        #pragma unroll
        for (int o = 4; o; o >>= 1) {
            s  += __shfl_xor_sync(0xffffffffu, s,  o);
            sq += __shfl_xor_sync(0xffffffffu, sq, o);
        }
        if (!l) { rs[0] = s * (1.f/DD); rq[0] = sq * (1.f/DD); }
    }
    __syncthreads();
    float mu = rs[0];
    float var = rq[0] - mu*mu;
    float rstd = rsqrtf(var + LNEPS);
    outr[t]     = f2tf32((v0-mu)*rstd*gam[t]     + bet[t]);
    outr[t+256] = f2tf32((v1-mu)*rstd*gam[t+256] + bet[t+256]);
    outr[t+512] = f2tf32((v2-mu)*rstd*gam[t+512] + bet[t+512]);
}

// ---------------------------------------------------------------------------
// 2. TF32 tensor-core NT GEMM: C[M][NC] = A[M][K] * W[NC][K]^T (+bias)
//    128x128 block tile, 8 warps (4x2), 32x64 per warp, k-step 16,
//    cp.async double-buffered stages. A and W are pre-rounded to tf32.
// ---------------------------------------------------------------------------
template<int M, int NC, int K, bool BIAS>
__device__ __forceinline__ void gemm_mma_body(const float* __restrict__ A,
                                              const float* __restrict__ W,
                                              const float* __restrict__ bias,
                                              float* __restrict__ C) {
    __shared__ float As[2][128][20];
    __shared__ float Ws[2][128][20];
    int tid = threadIdx.x;
    int w = tid >> 5, lane = tid & 31;
    int wm = w & 3;          // row quadrant: 32*wm
    int wn = w >> 2;         // col half:    64*wn
    int g  = lane >> 2;
    int tg = lane & 3;
    int rowBase = blockIdx.x * 128;
    int colBase = blockIdx.y * 128;

    float acc[2][8][4] = {};

    auto stage = [&](int buf, int kt) {
        #pragma unroll
        for (int s = 0; s < 2; s++) {
            int lin = tid + s*256;
            int r = lin >> 2, c = (lin & 3)*4;
            int gr = rowBase + r;
            cpa16(&As[buf][r][c], A + (size_t)gr*K + kt + c, gr < M);
            cpa16(&Ws[buf][r][c], W + (size_t)(colBase + r)*K + kt + c, true);
        }
        CP_COMMIT();
    };

    stage(0, 0);
    const int NKT = K / 16;
    for (int ki = 0; ki < NKT; ki++) {
        if (ki + 1 < NKT) { stage((ki+1)&1, (ki+1)*16); CP_WAIT(1); }
        else              { CP_WAIT(0); }
        __syncthreads();
        int buf = ki & 1;
        #pragma unroll
        for (int ks = 0; ks < 16; ks += 8) {
            unsigned a[2][4], bf[8][2];
            #pragma unroll
            for (int mt = 0; mt < 2; mt++) {
                int r0 = wm*32 + mt*16 + g;
                a[mt][0] = __float_as_uint(As[buf][r0  ][ks+tg  ]);
                a[mt][1] = __float_as_uint(As[buf][r0+8][ks+tg  ]);
                a[mt][2] = __float_as_uint(As[buf][r0  ][ks+tg+4]);
                a[mt][3] = __float_as_uint(As[buf][r0+8][ks+tg+4]);
            }
            #pragma unroll
            for (int nt = 0; nt < 8; nt++) {
                int c0 = wn*64 + nt*8 + g;
                bf[nt][0] = __float_as_uint(Ws[buf][c0][ks+tg  ]);
                bf[nt][1] = __float_as_uint(Ws[buf][c0][ks+tg+4]);
            }
            #pragma unroll
            for (int mt = 0; mt < 2; mt++)
                #pragma unroll
                for (int nt = 0; nt < 8; nt++)
                    mma_tf32(acc[mt][nt][0], acc[mt][nt][1], acc[mt][nt][2], acc[mt][nt][3],
                             a[mt][0], a[mt][1], a[mt][2], a[mt][3],
                             bf[nt][0], bf[nt][1]);
        }
        __syncthreads();
    }

    #pragma unroll
    for (int mt = 0; mt < 2; mt++) {
        int r_lo = rowBase + wm*32 + mt*16 + g;
        int r_hi = r_lo + 8;
        #pragma unroll
        for (int nt = 0; nt < 8; nt++) {
            int c = colBase + wn*64 + nt*8 + tg*2;
            float bx = 0.f, by = 0.f;
            if (BIAS) { bx = bias[c]; by = bias[c+1]; }
            if (r_lo < M) {
                float2 o; o.x = acc[mt][nt][0] + bx; o.y = acc[mt][nt][1] + by;
                *(float2*)(&C[(size_t)r_lo * NC + c]) = o;
            }
            if (r_hi < M) {
                float2 o; o.x = acc[mt][nt][2] + bx; o.y = acc[mt][nt][3] + by;
                *(float2*)(&C[(size_t)r_hi * NC + c]) = o;
            }
        }
    }
}

__global__ void __launch_bounds__(256) gemm_qkv_kernel() {
    gemm_mma_body<MR, EE, DD, false>(g_xn, g_wq, nullptr, g_qkv);
}
__global__ void __launch_bounds__(256) gemm_proj_kernel(const float* __restrict__ bias,
                                                        float* __restrict__ C) {
    gemm_mma_body<MR, DD, DD, true>(g_att, g_wp, bias, C);
}

// ---------------------------------------------------------------------------
// 3. RoPE + scatter qkv -> q,k,v in [B,H,N,64] layout.
//    q pre-scaled by 1/8 (exact) and all outputs tf32-rounded.
// ---------------------------------------------------------------------------
__global__ void rope_kernel() {
    int idx = blockIdx.x * 256 + threadIdx.x;
    if (idx >= MR * HH * 32) return;
    int p   = idx & 31;
    int tmp = idx >> 5;
    int h   = tmp % HH;
    int row = tmp / HH;          // b*NN + n
    int n = row % NN;
    int b = row / NN;
    int j, d0, t;
    if (p < 16) {
        j = p; d0 = 2*p;
        t = (n == 0) ? 0 : (n-1) / 32;        // row id
    } else {
        j = p - 16; d0 = 32 + 2*(p-16);
        t = (n == 0) ? 0 : (n-1) % 32;        // col id
    }
    float theta = (float)t * expf(-(float)j * 0.5756462732485115f);
    float s, c;
    sincosf(theta, &s, &c);
    const float* base = g_qkv + (size_t)row * EE + h*64;
    size_t o = ((size_t)(b*HH + h) * NN + n) * 64 + d0;
    float qe = base[d0],      qo = base[d0+1];
    g_q[o]   = f2tf32((qe*c - qo*s) * 0.125f);
    g_q[o+1] = f2tf32((qo*c + qe*s) * 0.125f);
    float ke = base[768+d0],  ko = base[768+d0+1];
    g_k[o]   = f2tf32(ke*c - ko*s);
    g_k[o+1] = f2tf32(ko*c + ke*s);
    g_v[o]   = f2tf32(base[1536+d0]);
    g_v[o+1] = f2tf32(base[1536+d0+1]);
}

// ---------------------------------------------------------------------------
// 4. FlashAttention-2 style: Q tile 128 rows, 8 warps x (16 rows x 64 cols).
//    Q frags + S + softmax + P all register-resident; K/V cp.async
//    double-buffered. grid (9, 12, 8), 256 threads.
// ---------------------------------------------------------------------------
#define KSP 68                       // K pitch (floats)  - QK b-frags conflict-free
#define VSP 72                       // V pitch (floats)  - PV b-frags conflict-free
#define KVBUF (64*KSP + 64*VSP)      // floats per stage buffer = 8960
#define NKB 17
__global__ void __launch_bounds__(256) attn_kernel() {
    extern __shared__ float sm[];
    int tid = threadIdx.x;
    int w = tid >> 5, lane = tid & 31;
    int g  = lane >> 2;
    int tg = lane & 3;
    int qb = blockIdx.x, h = blockIdx.y, b = blockIdx.z;
    size_t headOff = (size_t)(b*HH + h) * NN * 64;

    // ---- stage Q tile (128x64) into buffer 0 region, pitch KSP ----
    #pragma unroll
    for (int s = 0; s < 8; s++) {
        int lin = tid + s*256;
        int r = lin >> 4, c = (lin & 15)*4;
        int n = qb*128 + r;
        cpa16(&sm[r*KSP + c], g_q + headOff + (size_t)n*64 + c, n < NN);
    }
    CP_COMMIT();
    CP_WAIT(0);
    __syncthreads();

    // ---- Q fragments to registers (rows w*16+g, w*16+g+8) ----
    unsigned qa[8][4];
    {
        int r0 = w*16 + g;
        #pragma unroll
        for (int sl = 0; sl < 8; sl++) {
            int dk = sl*8;
            qa[sl][0] = __float_as_uint(sm[ r0   *KSP + dk+tg  ]);
            qa[sl][1] = __float_as_uint(sm[(r0+8)*KSP + dk+tg  ]);
            qa[sl][2] = __float_as_uint(sm[ r0   *KSP + dk+tg+4]);
            qa[sl][3] = __float_as_uint(sm[(r0+8)*KSP + dk+tg+4]);
        }
    }
    __syncthreads();

    auto stage_kv = [&](int buf, int kb) {
        float* KsB = sm + buf*KVBUF;
        float* VsB = KsB + 64*KSP;
        #pragma unroll
        for (int s = 0; s < 4; s++) {
            int lin = tid + s*256;
            int r = lin >> 4, c = (lin & 15)*4;
            int n = kb*64 + r;
            bool ok = n < NN;
            cpa16(&KsB[r*KSP + c], g_k + headOff + (size_t)n*64 + c, ok);
            cpa16(&VsB[r*VSP + c], g_v + headOff + (size_t)n*64 + c, ok);
        }
        CP_COMMIT();
    };

    stage_kv(0, 0);

    float m0 = -1e30f, m1 = -1e30f, l0 = 0.f, l1 = 0.f;
    float acc[8][4] = {};

    for (int kb = 0; kb < NKB; kb++) {
        if (kb + 1 < NKB) { stage_kv((kb+1)&1, kb+1); CP_WAIT(1); }
        else              { CP_WAIT(0); }
        __syncthreads();
        const float* Ks = sm + (kb&1)*KVBUF;
        const float* Vs = Ks + 64*KSP;

        // ---- S = Q @ K^T (pre-scaled by 1/8 via Q) ----
        float s4[8][4] = {};
        #pragma unroll
        for (int sl = 0; sl < 8; sl++) {
            int dk = sl*8;
            #pragma unroll
            for (int nt = 0; nt < 8; nt++) {
                int c0 = nt*8 + g;
                unsigned b0 = __float_as_uint(Ks[c0*KSP + dk+tg  ]);
                unsigned b1 = __float_as_uint(Ks[c0*KSP + dk+tg+4]);
                mma_tf32(s4[nt][0], s4[nt][1], s4[nt][2], s4[nt][3],
                         qa[sl][0], qa[sl][1], qa[sl][2], qa[sl][3], b0, b1);
            }
        }

        // ---- mask last tile ----
        if (kb == NKB-1) {
            #pragma unroll
            for (int nt = 0; nt < 8; nt++) {
                int cg = (NKB-1)*64 + nt*8 + tg*2;
                if (cg   >= NN) { s4[nt][0] = -1e30f; s4[nt][2] = -1e30f; }
                if (cg+1 >= NN) { s4[nt][1] = -1e30f; s4[nt][3] = -1e30f; }
            }
        }

        // ---- online softmax in registers ----
        float mx0 = -1e30f, mx1 = -1e30f;
        #pragma unroll
        for (int nt = 0; nt < 8; nt++) {
            mx0 = fmaxf(mx0, fmaxf(s4[nt][0], s4[nt][1]));
            mx1 = fmaxf(mx1, fmaxf(s4[nt][2], s4[nt][3]));
        }
        mx0 = fmaxf(mx0, __shfl_xor_sync(0xffffffffu, mx0, 1));
        mx0 = fmaxf(mx0, __shfl_xor_sync(0xffffffffu, mx0, 2));
        mx1 = fmaxf(mx1, __shfl_xor_sync(0xffffffffu, mx1, 1));
        mx1 = fmaxf(mx1, __shfl_xor_sync(0xffffffffu, mx1, 2));
        float m0n = fmaxf(m0, mx0), m1n = fmaxf(m1, mx1);
        float al0 = __expf(m0 - m0n), al1 = __expf(m1 - m1n);
        float sum0 = 0.f, sum1 = 0.f;
        #pragma unroll
        for (int nt = 0; nt < 8; nt++) {
            float p0 = f2tf32(__expf(s4[nt][0] - m0n));
            float p1 = f2tf32(__expf(s4[nt][1] - m0n));
            float p2 = f2tf32(__expf(s4[nt][2] - m1n));
            float p3 = f2tf32(__expf(s4[nt][3] - m1n));
            sum0 += p0 + p1; sum1 += p2 + p3;
            s4[nt][0] = p0; s4[nt][1] = p1; s4[nt][2] = p2; s4[nt][3] = p3;
        }
        sum0 += __shfl_xor_sync(0xffffffffu, sum0, 1);
        sum0 += __shfl_xor_sync(0xffffffffu, sum0, 2);
        sum1 += __shfl_xor_sync(0xffffffffu, sum1, 1);
        sum1 += __shfl_xor_sync(0xffffffffu, sum1, 2);
        l0 = l0*al0 + sum0; l1 = l1*al1 + sum1;
        m0 = m0n; m1 = m1n;
        #pragma unroll
        for (int nt = 0; nt < 8; nt++) {
            acc[nt][0] *= al0; acc[nt][1] *= al0;
            acc[nt][2] *= al1; acc[nt][3] *= al1;
        }

        // ---- acc += P @ V : A-frags from registers via quad shuffles ----
        int srcA = (lane & ~3) + (tg >> 1);
        int srcB = srcA + 2;
        #pragma unroll
        for (int jt = 0; jt < 8; jt++) {
            float v00 = __shfl_sync(0xffffffffu, s4[jt][0], srcA);
            float v01 = __shfl_sync(0xffffffffu, s4[jt][1], srcA);
            float v10 = __shfl_sync(0xffffffffu, s4[jt][2], srcA);
            float v11 = __shfl_sync(0xffffffffu, s4[jt][3], srcA);
            float w00 = __shfl_sync(0xffffffffu, s4[jt][0], srcB);
            float w01 = __shfl_sync(0xffffffffu, s4[jt][1], srcB);
            float w10 = __shfl_sync(0xffffffffu, s4[jt][2], srcB);
            float w11 = __shfl_sync(0xffffffffu, s4[jt][3], srcB);
            unsigned a0 = __float_as_uint((tg & 1) ? v01 : v00);
            unsigned a1 = __float_as_uint((tg & 1) ? v11 : v10);
            unsigned a2 = __float_as_uint((tg & 1) ? w01 : w00);
            unsigned a3 = __float_as_uint((tg & 1) ? w11 : w10);
            int j0 = jt*8;
            #pragma unroll
            for (int nt = 0; nt < 8; nt++) {
                int c0 = nt*8 + g;
                unsigned b0 = __float_as_uint(Vs[(j0+tg  )*VSP + c0]);
                unsigned b1 = __float_as_uint(Vs[(j0+tg+4)*VSP + c0]);
                mma_tf32(acc[nt][0], acc[nt][1], acc[nt][2], acc[nt][3],
                         a0, a1, a2, a3, b0, b1);
            }
        }
        __syncthreads();
    }

    // ---- normalize + write (tf32-rounded for the proj GEMM) ----
    {
        int n0 = qb*128 + w*16 + g;
        int n1 = n0 + 8;
        float linv0 = 1.f / l0, linv1 = 1.f / l1;
        #pragma unroll
        for (int nt = 0; nt < 8; nt++) {
            int d = nt*8 + tg*2;
            if (n0 < NN) {
                float2 o;
                o.x = f2tf32(acc[nt][0]*linv0);
                o.y = f2tf32(acc[nt][1]*linv0);
                *(float2*)(&g_att[((size_t)b*NN + n0)*DD + h*64 + d]) = o;
            }
            if (n1 < NN) {
                float2 o;
                o.x = f2tf32(acc[nt][2]*linv1);
                o.y = f2tf32(acc[nt][3]*linv1);
                *(float2*)(&g_att[((size_t)b*NN + n1)*DD + h*64 + d]) = o;
            }
        }
    }
}

// ---------------------------------------------------------------------------
// Launch
// ---------------------------------------------------------------------------
extern "C" void kernel_launch(void* const* d_in, const int* in_sizes, int n_in,
                              void* d_out, int out_size) {
    const float* x      = (const float*)d_in[0];
    const float* ln_g   = (const float*)d_in[1];
    const float* ln_b   = (const float*)d_in[2];
    const float* w_qkv  = (const float*)d_in[3];
    const float* w_proj = (const float*)d_in[4];
    const float* b_proj = (const float*)d_in[5];
    float* out = (float*)d_out;

    const int ATT_SMEM = 2 * KVBUF * sizeof(float);   // 71680 B
    cudaFuncSetAttribute(attn_kernel, cudaFuncAttributeMaxDynamicSharedMemorySize, ATT_SMEM);

    const int RW = (EE*DD/4 + DD*DD/4 + 255) / 256;
    roundw_kernel<<<RW, 256>>>((const float4*)w_qkv, (const float4*)w_proj);
    ln_kernel<<<MR, 256>>>(x, ln_g, ln_b);
    gemm_qkv_kernel<<<dim3((MR+127)/128, EE/128), 256>>>();
    rope_kernel<<<(MR*HH*32 + 255)/256, 256>>>();
    attn_kernel<<<dim3((NN+127)/128, HH, BB), 256, ATT_SMEM>>>();
    gemm_proj_kernel<<<dim3((MR+127)/128, DD/128), 256>>>(b_proj, out);
}